// round 9
// baseline (speedup 1.0000x reference)
#include <cuda_runtime.h>
#include <cuda_fp16.h>
#include <cstdint>

// SoftmaxSelfAttention B=2,H=16,S=2048,D=64 fp32.
// Round 9: pure-fp16 HMMA flash attention. 128-thread CTAs, 4 warps x 32
// q-rows (1 smem wavefront per MMA), 2-stage cp.async pipeline, 3 CTAs/SM
// (12 warps/SM for latency hiding; 1.15 waves).

#define SEQi  2048
#define Dhi   64
#define TMi   128
#define TNi   128
#define NTi   (SEQi / TNi)
#define PADHi 72            // halves per smem row (144B rows, LDSM conflict-free)
#define ROWBi 144
#define TILEBi (TNi * ROWBi)              // 18432 B per tile buffer
#define NELEMi ((size_t)32 * SEQi * Dhi)  // elements per tensor

__device__ __align__(16) __half gKh[NELEMi];
__device__ __align__(16) __half gVh[NELEMi];

namespace {
constexpr int SM_BUF   = 2048;                  // bias [2][128] floats at 0
constexpr int STAGEB   = 2 * TILEBi;            // K+V per stage
constexpr int SM_TOTAL = SM_BUF + 2 * STAGEB;   // 75776 B -> 3 CTAs/SM
constexpr float SCL = 0.18033688011112042f;     // log2(e)/8
constexpr float L2E = 1.4426950408889634f;
}

__device__ __forceinline__ uint32_t s2u(const void* p) {
    uint32_t a;
    asm("{ .reg .u64 t; cvta.to.shared.u64 t, %1; cvt.u32.u64 %0, t; }" : "=r"(a) : "l"(p));
    return a;
}
__device__ __forceinline__ void ldx4(uint32_t r[4], uint32_t a) {
    asm volatile("ldmatrix.sync.aligned.m8n8.x4.shared.b16 {%0,%1,%2,%3}, [%4];"
                 : "=r"(r[0]), "=r"(r[1]), "=r"(r[2]), "=r"(r[3]) : "r"(a));
}
__device__ __forceinline__ void ldx4t(uint32_t r[4], uint32_t a) {
    asm volatile("ldmatrix.sync.aligned.m8n8.x4.trans.shared.b16 {%0,%1,%2,%3}, [%4];"
                 : "=r"(r[0]), "=r"(r[1]), "=r"(r[2]), "=r"(r[3]) : "r"(a));
}
__device__ __forceinline__ void mma16816(float c[4], const uint32_t a[4],
                                         uint32_t b0, uint32_t b1) {
    asm("mma.sync.aligned.m16n8k16.row.col.f32.f16.f16.f32 "
        "{%0,%1,%2,%3}, {%4,%5,%6,%7}, {%8,%9}, {%0,%1,%2,%3};"
        : "+f"(c[0]), "+f"(c[1]), "+f"(c[2]), "+f"(c[3])
        : "r"(a[0]), "r"(a[1]), "r"(a[2]), "r"(a[3]), "r"(b0), "r"(b1));
}
__device__ __forceinline__ float ex2(float x) {
    float r; asm("ex2.approx.ftz.f32 %0, %1;" : "=f"(r) : "f"(x)); return r;
}
__device__ __forceinline__ uint32_t pack2h(float a, float b) {
    uint32_t h;
    asm("cvt.rn.f16x2.f32 %0, %1, %2;" : "=r"(h) : "f"(b), "f"(a));
    return h;
}

// ---------------- pre-pass: fp32 K/V -> fp16 scratch ----------------
__global__ __launch_bounds__(256)
void conv_kernel(const float* __restrict__ K, const float* __restrict__ V)
{
    size_t e = (size_t)blockIdx.x * 256 + threadIdx.x;   // float4 index
    const float* src = blockIdx.y ? V : K;
    __half* dst = blockIdx.y ? gVh : gKh;
    float4 x = __ldg((const float4*)src + e);
    *(uint2*)(dst + e * 4) = make_uint2(pack2h(x.x, x.y), pack2h(x.z, x.w));
}

// prefetch one 128x64 fp16 tile (1024 x 16B chunks) with 128 threads
__device__ __forceinline__ void prefetch_tile(uint32_t sdst, const __half* gsrc, int tid)
{
    #pragma unroll
    for (int j = 0; j < 8; j++) {
        int chunk = tid + j * 128;
        int row = chunk >> 3, c8 = chunk & 7;
        uint32_t d = sdst + (uint32_t)(row * ROWBi + c8 * 16);
        unsigned long long s =
            (unsigned long long)__cvta_generic_to_global(gsrc + (size_t)row * Dhi + c8 * 8);
        asm volatile("cp.async.cg.shared.global [%0], [%1], 16;" :: "r"(d), "l"(s));
    }
}

__global__ __launch_bounds__(128, 3)
void fa_hmma_kernel(const float* __restrict__ Q, const float* __restrict__ Mk,
                    float* __restrict__ O)
{
    extern __shared__ char sm[];
    float* biasB = (float*)sm;                 // [2][128] per-stage mask bias
    const uint32_t sb = s2u(sm);
    const uint32_t sK[2] = {sb + SM_BUF, sb + SM_BUF + STAGEB};
    const uint32_t sV[2] = {sK[0] + TILEBi, sK[1] + TILEBi};

    const int tid = threadIdx.x, wid = tid >> 5, lid = tid & 31;
    const int qt = blockIdx.x, bh = blockIdx.y, b = bh >> 4;

    const float* Qb = Q + ((size_t)bh * SEQi + (size_t)qt * TMi) * Dhi;
    const float* mb = Mk + (size_t)b * SEQi;
    const size_t kbase = (size_t)bh * SEQi * Dhi;

    // ---- stage Q (fp32 -> fp16) through stage-0 K buffer ----
    #pragma unroll
    for (int v = 0; v < 16; v++) {
        int e = tid + v * 128;            // 2048 float4 of the 128x64 tile
        int r = e >> 4, c4 = e & 15;
        float4 q4 = __ldg((const float4*)(Qb + r * Dhi + c4 * 4));
        uint32_t byt = (uint32_t)(r * ROWBi + c4 * 8);
        *(uint2*)(sm + SM_BUF + byt) = make_uint2(pack2h(q4.x, q4.y), pack2h(q4.z, q4.w));
    }
    __syncthreads();

    // Q fragments: each warp owns 32 rows = 2 row-groups of 16
    uint32_t qf[2][4][4];
    #pragma unroll
    for (int rg = 0; rg < 2; rg++) {
        int qrow = wid * 32 + rg * 16 + (lid & 15);
        #pragma unroll
        for (int j = 0; j < 4; j++) {
            uint32_t off = (uint32_t)(qrow * PADHi + j * 16 + ((lid >> 4) << 3)) * 2;
            ldx4(qf[rg][j], sK[0] + off);
        }
    }
    __syncthreads();   // Q frags in regs; stage-0 buffer reusable

    // prefetch tile 0 into stage 0; build bias slice 0
    prefetch_tile(sK[0], gKh + kbase, tid);
    prefetch_tile(sV[0], gVh + kbase, tid);
    asm volatile("cp.async.commit_group;" ::: "memory");
    biasB[tid] = -1.0e6f * (1.0f - __ldg(&mb[tid])) * L2E;

    float o[2][8][4];
    #pragma unroll
    for (int rg = 0; rg < 2; rg++)
        #pragma unroll
        for (int i = 0; i < 8; i++)
            #pragma unroll
            for (int j = 0; j < 4; j++) o[rg][i][j] = 0.0f;
    float lsum[2][2] = {{0.f, 0.f}, {0.f, 0.f}};

    for (int kt = 0; kt < NTi; kt++) {
        const int stg = kt & 1;
        asm volatile("cp.async.wait_group 0;" ::: "memory");
        __syncthreads();   // tile kt visible; all warps done with other stage

        if (kt + 1 < NTi) {   // prefetch next tile into the other stage
            const size_t tb = kbase + (size_t)(kt + 1) * TNi * Dhi;
            prefetch_tile(sK[stg ^ 1], gKh + tb, tid);
            prefetch_tile(sV[stg ^ 1], gVh + tb, tid);
            asm volatile("cp.async.commit_group;" ::: "memory");
            biasB[(stg ^ 1) * 128 + tid] =
                -1.0e6f * (1.0f - __ldg(&mb[(kt + 1) * TNi + tid])) * L2E;
        }
        const uint32_t sKh = sK[stg], sVh = sV[stg];
        const float* biasT = biasB + stg * 128;

        #pragma unroll
        for (int pair = 0; pair < 8; pair++) {
            uint32_t ap[2][4];   // P A-fragments for both row-groups

            // ---- per 8-key half: QK^T -> softmax -> pack (register-lean) ----
            #pragma unroll
            for (int half = 0; half < 2; half++) {
                int key = pair * 16 + half * 8 + (lid & 7);
                uint32_t off = (uint32_t)(key * PADHi + ((lid >> 3) << 3)) * 2;
                uint32_t kh8[8];
                ldx4(&kh8[0], sKh + off);
                ldx4(&kh8[4], sKh + off + 64);

                float b0 = biasT[pair * 16 + half * 8 + 2 * (lid & 3)];
                float b1 = biasT[pair * 16 + half * 8 + 2 * (lid & 3) + 1];

                #pragma unroll
                for (int rg = 0; rg < 2; rg++) {
                    float a1[4] = {0.f, 0.f, 0.f, 0.f};
                    float a2[4] = {0.f, 0.f, 0.f, 0.f};
                    #pragma unroll
                    for (int j = 0; j < 4; j++)
                        mma16816((j & 1) ? a2 : a1, qf[rg][j], kh8[2 * j], kh8[2 * j + 1]);
                    float s0 = ex2(fmaf(a1[0] + a2[0], SCL, b0));
                    float s1 = ex2(fmaf(a1[1] + a2[1], SCL, b1));
                    float s2 = ex2(fmaf(a1[2] + a2[2], SCL, b0));
                    float s3 = ex2(fmaf(a1[3] + a2[3], SCL, b1));
                    lsum[rg][0] += s0 + s1;
                    lsum[rg][1] += s2 + s3;
                    ap[rg][half * 2]     = pack2h(s0, s1);
                    ap[rg][half * 2 + 1] = pack2h(s2, s3);
                }
            }

            // ---- O += P·V over these 16 keys (V frags reused for both rg) ----
            int keyr = pair * 16 + (lid & 15);
            #pragma unroll
            for (int np = 0; np < 4; np++) {
                uint32_t off = (uint32_t)(keyr * PADHi + np * 16 + ((lid >> 4) << 3)) * 2;
                uint32_t vh[4];
                ldx4t(vh, sVh + off);
                #pragma unroll
                for (int rg = 0; rg < 2; rg++) {
                    mma16816(o[rg][2 * np],     ap[rg], vh[0], vh[1]);
                    mma16816(o[rg][2 * np + 1], ap[rg], vh[2], vh[3]);
                }
            }
        }
    }

    // ---- epilogue: row sums across quad lanes, divide, store ----
    float* Ob = O + ((size_t)bh * SEQi + (size_t)qt * TMi) * Dhi;
    #pragma unroll
    for (int rg = 0; rg < 2; rg++) {
        float l0 = lsum[rg][0], l1 = lsum[rg][1];
        l0 += __shfl_xor_sync(0xffffffffu, l0, 1);
        l0 += __shfl_xor_sync(0xffffffffu, l0, 2);
        l1 += __shfl_xor_sync(0xffffffffu, l1, 1);
        l1 += __shfl_xor_sync(0xffffffffu, l1, 2);
        float inv0 = 1.0f / l0, inv1 = 1.0f / l1;

        int row0 = wid * 32 + rg * 16 + (lid >> 2);
        int col  = 2 * (lid & 3);
        #pragma unroll
        for (int nt = 0; nt < 8; nt++) {
            int c = nt * 8 + col;
            *(float2*)(Ob + (size_t)row0 * Dhi + c) =
                make_float2(o[rg][nt][0] * inv0, o[rg][nt][1] * inv0);
            *(float2*)(Ob + (size_t)(row0 + 8) * Dhi + c) =
                make_float2(o[rg][nt][2] * inv1, o[rg][nt][3] * inv1);
        }
    }
}

extern "C" void kernel_launch(void* const* d_in, const int* in_sizes, int n_in,
                              void* d_out, int out_size)
{
    const float* Q = (const float*)d_in[0];
    const float* K = (const float*)d_in[1];
    const float* V = (const float*)d_in[2];
    const float* M = (const float*)d_in[3];
    float* O = (float*)d_out;

    conv_kernel<<<dim3(4096, 2), 256>>>(K, V);

    cudaFuncSetAttribute(fa_hmma_kernel,
                         cudaFuncAttributeMaxDynamicSharedMemorySize, SM_TOTAL);
    dim3 grid(SEQi / TMi, 32);   // x-major: same-head CTAs coresident -> L2 reuse
    fa_hmma_kernel<<<grid, 128, SM_TOTAL>>>(Q, M, O);
}

// round 10
// speedup vs baseline: 1.0980x; 1.0980x over previous
#include <cuda_runtime.h>
#include <cuda_fp16.h>
#include <cstdint>

// SoftmaxSelfAttention B=2,H=16,S=2048,D=64 fp32.
// Round 10: pure-fp16 HMMA flash attention. 128-thread CTAs, 4 warps x 32
// q-rows, 2-stage cp.async pipeline, 3 CTAs/SM. Row-sums (softmax denom)
// computed ON THE TENSOR PIPE via a constant ones-column B-fragment MMA;
// single-accumulator QK chains. Minimizes non-MMA issue slots per pair.

#define SEQi  2048
#define Dhi   64
#define TMi   128
#define TNi   128
#define NTi   (SEQi / TNi)
#define PADHi 72            // halves per smem row (144B rows, LDSM conflict-free)
#define ROWBi 144
#define TILEBi (TNi * ROWBi)              // 18432 B per tile buffer
#define NELEMi ((size_t)32 * SEQi * Dhi)  // elements per tensor

__device__ __align__(16) __half gKh[NELEMi];
__device__ __align__(16) __half gVh[NELEMi];

namespace {
constexpr int SM_BUF   = 2048;                  // bias [2][128] floats at 0
constexpr int STAGEB   = 2 * TILEBi;            // K+V per stage
constexpr int SM_TOTAL = SM_BUF + 2 * STAGEB;   // 75776 B -> 3 CTAs/SM
constexpr float SCL = 0.18033688011112042f;     // log2(e)/8
constexpr float L2E = 1.4426950408889634f;
}

__device__ __forceinline__ uint32_t s2u(const void* p) {
    uint32_t a;
    asm("{ .reg .u64 t; cvta.to.shared.u64 t, %1; cvt.u32.u64 %0, t; }" : "=r"(a) : "l"(p));
    return a;
}
__device__ __forceinline__ void ldx4(uint32_t r[4], uint32_t a) {
    asm volatile("ldmatrix.sync.aligned.m8n8.x4.shared.b16 {%0,%1,%2,%3}, [%4];"
                 : "=r"(r[0]), "=r"(r[1]), "=r"(r[2]), "=r"(r[3]) : "r"(a));
}
__device__ __forceinline__ void ldx4t(uint32_t r[4], uint32_t a) {
    asm volatile("ldmatrix.sync.aligned.m8n8.x4.trans.shared.b16 {%0,%1,%2,%3}, [%4];"
                 : "=r"(r[0]), "=r"(r[1]), "=r"(r[2]), "=r"(r[3]) : "r"(a));
}
__device__ __forceinline__ void mma16816(float c[4], const uint32_t a[4],
                                         uint32_t b0, uint32_t b1) {
    asm("mma.sync.aligned.m16n8k16.row.col.f32.f16.f16.f32 "
        "{%0,%1,%2,%3}, {%4,%5,%6,%7}, {%8,%9}, {%0,%1,%2,%3};"
        : "+f"(c[0]), "+f"(c[1]), "+f"(c[2]), "+f"(c[3])
        : "r"(a[0]), "r"(a[1]), "r"(a[2]), "r"(a[3]), "r"(b0), "r"(b1));
}
__device__ __forceinline__ float ex2(float x) {
    float r; asm("ex2.approx.ftz.f32 %0, %1;" : "=f"(r) : "f"(x)); return r;
}
__device__ __forceinline__ uint32_t pack2h(float a, float b) {
    uint32_t h;
    asm("cvt.rn.f16x2.f32 %0, %1, %2;" : "=r"(h) : "f"(b), "f"(a));
    return h;
}

// ---------------- pre-pass: fp32 K/V -> fp16 scratch ----------------
__global__ __launch_bounds__(256)
void conv_kernel(const float* __restrict__ K, const float* __restrict__ V)
{
    size_t e = (size_t)blockIdx.x * 256 + threadIdx.x;   // float4 index
    const float* src = blockIdx.y ? V : K;
    __half* dst = blockIdx.y ? gVh : gKh;
    float4 x = __ldg((const float4*)src + e);
    *(uint2*)(dst + e * 4) = make_uint2(pack2h(x.x, x.y), pack2h(x.z, x.w));
}

// prefetch one 128x64 fp16 tile (1024 x 16B chunks) with 128 threads
__device__ __forceinline__ void prefetch_tile(uint32_t sdst, const __half* gsrc, int tid)
{
    #pragma unroll
    for (int j = 0; j < 8; j++) {
        int chunk = tid + j * 128;
        int row = chunk >> 3, c8 = chunk & 7;
        uint32_t d = sdst + (uint32_t)(row * ROWBi + c8 * 16);
        unsigned long long s =
            (unsigned long long)__cvta_generic_to_global(gsrc + (size_t)row * Dhi + c8 * 8);
        asm volatile("cp.async.cg.shared.global [%0], [%1], 16;" :: "r"(d), "l"(s));
    }
}

__global__ __launch_bounds__(128, 3)
void fa_hmma_kernel(const float* __restrict__ Q, const float* __restrict__ Mk,
                    float* __restrict__ O)
{
    extern __shared__ char sm[];
    float* biasB = (float*)sm;                 // [2][128] per-stage mask bias
    const uint32_t sb = s2u(sm);
    const uint32_t sK[2] = {sb + SM_BUF, sb + SM_BUF + STAGEB};
    const uint32_t sV[2] = {sK[0] + TILEBi, sK[1] + TILEBi};

    const int tid = threadIdx.x, wid = tid >> 5, lid = tid & 31;
    const int qt = blockIdx.x, bh = blockIdx.y, b = bh >> 4;

    const float* Qb = Q + ((size_t)bh * SEQi + (size_t)qt * TMi) * Dhi;
    const float* mb = Mk + (size_t)b * SEQi;
    const size_t kbase = (size_t)bh * SEQi * Dhi;

    // constant B-fragment for the ones column (n=0): lanes 0-3 hold n=0,
    // all k; fp16 1.0 = 0x3C00 packed pairwise.
    const uint32_t onesb = (lid < 4) ? 0x3C003C00u : 0u;

    // ---- stage Q (fp32 -> fp16) through stage-0 K buffer ----
    #pragma unroll
    for (int v = 0; v < 16; v++) {
        int e = tid + v * 128;            // 2048 float4 of the 128x64 tile
        int r = e >> 4, c4 = e & 15;
        float4 q4 = __ldg((const float4*)(Qb + r * Dhi + c4 * 4));
        uint32_t byt = (uint32_t)(r * ROWBi + c4 * 8);
        *(uint2*)(sm + SM_BUF + byt) = make_uint2(pack2h(q4.x, q4.y), pack2h(q4.z, q4.w));
    }
    __syncthreads();

    // Q fragments: each warp owns 32 rows = 2 row-groups of 16
    uint32_t qf[2][4][4];
    #pragma unroll
    for (int rg = 0; rg < 2; rg++) {
        int qrow = wid * 32 + rg * 16 + (lid & 15);
        #pragma unroll
        for (int j = 0; j < 4; j++) {
            uint32_t off = (uint32_t)(qrow * PADHi + j * 16 + ((lid >> 4) << 3)) * 2;
            ldx4(qf[rg][j], sK[0] + off);
        }
    }
    __syncthreads();   // Q frags in regs; stage-0 buffer reusable

    // prefetch tile 0 into stage 0; build bias slice 0
    prefetch_tile(sK[0], gKh + kbase, tid);
    prefetch_tile(sV[0], gVh + kbase, tid);
    asm volatile("cp.async.commit_group;" ::: "memory");
    biasB[tid] = -1.0e6f * (1.0f - __ldg(&mb[tid])) * L2E;

    float o[2][8][4];
    float ox[2][4];     // ones-column accumulator: row sums of P
    #pragma unroll
    for (int rg = 0; rg < 2; rg++) {
        #pragma unroll
        for (int i = 0; i < 8; i++)
            #pragma unroll
            for (int j = 0; j < 4; j++) o[rg][i][j] = 0.0f;
        #pragma unroll
        for (int j = 0; j < 4; j++) ox[rg][j] = 0.0f;
    }

    for (int kt = 0; kt < NTi; kt++) {
        const int stg = kt & 1;
        asm volatile("cp.async.wait_group 0;" ::: "memory");
        __syncthreads();   // tile kt visible; all warps done with other stage

        if (kt + 1 < NTi) {   // prefetch next tile into the other stage
            const size_t tb = kbase + (size_t)(kt + 1) * TNi * Dhi;
            prefetch_tile(sK[stg ^ 1], gKh + tb, tid);
            prefetch_tile(sV[stg ^ 1], gVh + tb, tid);
            asm volatile("cp.async.commit_group;" ::: "memory");
            biasB[(stg ^ 1) * 128 + tid] =
                -1.0e6f * (1.0f - __ldg(&mb[(kt + 1) * TNi + tid])) * L2E;
        }
        const uint32_t sKh = sK[stg], sVh = sV[stg];
        const float* biasT = biasB + stg * 128;

        #pragma unroll
        for (int pair = 0; pair < 8; pair++) {
            uint32_t ap[2][4];   // P A-fragments for both row-groups

            // ---- per 8-key half: QK^T -> softmax -> pack ----
            #pragma unroll
            for (int half = 0; half < 2; half++) {
                int key = pair * 16 + half * 8 + (lid & 7);
                uint32_t off = (uint32_t)(key * PADHi + ((lid >> 3) << 3)) * 2;
                uint32_t kh8[8];
                ldx4(&kh8[0], sKh + off);
                ldx4(&kh8[4], sKh + off + 64);

                float b0 = biasT[pair * 16 + half * 8 + 2 * (lid & 3)];
                float b1 = biasT[pair * 16 + half * 8 + 2 * (lid & 3) + 1];

                #pragma unroll
                for (int rg = 0; rg < 2; rg++) {
                    float acc[4] = {0.f, 0.f, 0.f, 0.f};
                    #pragma unroll
                    for (int j = 0; j < 4; j++)
                        mma16816(acc, qf[rg][j], kh8[2 * j], kh8[2 * j + 1]);
                    float s0 = ex2(fmaf(acc[0], SCL, b0));
                    float s1 = ex2(fmaf(acc[1], SCL, b1));
                    float s2 = ex2(fmaf(acc[2], SCL, b0));
                    float s3 = ex2(fmaf(acc[3], SCL, b1));
                    ap[rg][half * 2]     = pack2h(s0, s1);
                    ap[rg][half * 2 + 1] = pack2h(s2, s3);
                }
            }

            // ---- row sums of P on the tensor pipe: ox += P · ones ----
            mma16816(ox[0], ap[0], onesb, onesb);
            mma16816(ox[1], ap[1], onesb, onesb);

            // ---- O += P·V over these 16 keys (V frags reused for both rg) ----
            int keyr = pair * 16 + (lid & 15);
            #pragma unroll
            for (int np = 0; np < 4; np++) {
                uint32_t off = (uint32_t)(keyr * PADHi + np * 16 + ((lid >> 4) << 3)) * 2;
                uint32_t vh[4];
                ldx4t(vh, sVh + off);
                #pragma unroll
                for (int rg = 0; rg < 2; rg++) {
                    mma16816(o[rg][2 * np],     ap[rg], vh[0], vh[1]);
                    mma16816(o[rg][2 * np + 1], ap[rg], vh[2], vh[3]);
                }
            }
        }
    }

    // ---- epilogue: row sum lives in ox col 0 (lane lid&~3), divide, store ----
    float* Ob = O + ((size_t)bh * SEQi + (size_t)qt * TMi) * Dhi;
    #pragma unroll
    for (int rg = 0; rg < 2; rg++) {
        float l0 = __shfl_sync(0xffffffffu, ox[rg][0], lid & 28);
        float l1 = __shfl_sync(0xffffffffu, ox[rg][2], lid & 28);
        float inv0 = 1.0f / l0, inv1 = 1.0f / l1;

        int row0 = wid * 32 + rg * 16 + (lid >> 2);
        int col  = 2 * (lid & 3);
        #pragma unroll
        for (int nt = 0; nt < 8; nt++) {
            int c = nt * 8 + col;
            *(float2*)(Ob + (size_t)row0 * Dhi + c) =
                make_float2(o[rg][nt][0] * inv0, o[rg][nt][1] * inv0);
            *(float2*)(Ob + (size_t)(row0 + 8) * Dhi + c) =
                make_float2(o[rg][nt][2] * inv1, o[rg][nt][3] * inv1);
        }
    }
}

extern "C" void kernel_launch(void* const* d_in, const int* in_sizes, int n_in,
                              void* d_out, int out_size)
{
    const float* Q = (const float*)d_in[0];
    const float* K = (const float*)d_in[1];
    const float* V = (const float*)d_in[2];
    const float* M = (const float*)d_in[3];
    float* O = (float*)d_out;

    conv_kernel<<<dim3(4096, 2), 256>>>(K, V);

    cudaFuncSetAttribute(fa_hmma_kernel,
                         cudaFuncAttributeMaxDynamicSharedMemorySize, SM_TOTAL);
    dim3 grid(SEQi / TMi, 32);   // x-major: same-head CTAs coresident -> L2 reuse
    fa_hmma_kernel<<<grid, 128, SM_TOTAL>>>(Q, M, O);
}